// round 1
// baseline (speedup 1.0000x reference)
#include <cuda_runtime.h>
#include <stdint.h>

// ---------------------------------------------------------------------------
// SymmetricRBM: CD-k loss with symmetrized free energy, bit-exact JAX threefry.
// ---------------------------------------------------------------------------

#define PARTITIONABLE 1   // jax_threefry_partitionable (default True since jax 0.4.36)

#define Bn 8192
#define Vn 1024
#define Hn 1024
#define KSTEPS 10

// ------------------------- scratch (device globals) -------------------------
__device__ float    g_v[Bn * Vn];     // chain state v
__device__ float    g_vbr[Bn * Vn];   // v_branch
__device__ float    g_s[Bn * Hn];     // pre-activations / vW scratch
__device__ float    g_h[Bn * Hn];     // hidden samples
__device__ float    g_a[Bn * Vn];     // h @ W^T
__device__ float    g_Wt[Hn * Vn];    // W transpose
__device__ float    g_wcol[Hn];       // W.sum(axis=0)
__device__ float    g_u[Bn];          // flip indicator u
__device__ float    g_bsum;           // b.sum()
__device__ uint32_t g_keys[2 + 6 * KSTEPS];
__device__ double   g_acc[2];         // sum F(v_data), sum F(v_model)

// ------------------------------ threefry2x32 -------------------------------
__device__ __forceinline__ uint32_t rotl_(uint32_t x, int r) {
    return (x << r) | (x >> (32 - r));
}

__device__ __forceinline__ void tf2x32(uint32_t k0, uint32_t k1,
                                       uint32_t x0, uint32_t x1,
                                       uint32_t& o0, uint32_t& o1) {
    uint32_t ks2 = k0 ^ k1 ^ 0x1BD11BDAu;
    x0 += k0; x1 += k1;
#define TF_R4(a,b,c,d) \
    x0 += x1; x1 = rotl_(x1, a); x1 ^= x0; \
    x0 += x1; x1 = rotl_(x1, b); x1 ^= x0; \
    x0 += x1; x1 = rotl_(x1, c); x1 ^= x0; \
    x0 += x1; x1 = rotl_(x1, d); x1 ^= x0;
    TF_R4(13, 15, 26, 6)
    x0 += k1;  x1 += ks2 + 1u;
    TF_R4(17, 29, 16, 24)
    x0 += ks2; x1 += k0 + 2u;
    TF_R4(13, 15, 26, 6)
    x0 += k0;  x1 += k1 + 3u;
    TF_R4(17, 29, 16, 24)
    x0 += k1;  x1 += ks2 + 4u;
    TF_R4(13, 15, 26, 6)
    x0 += ks2; x1 += k0 + 5u;
#undef TF_R4
    o0 = x0; o1 = x1;
}

// random bits for flat index i in an array of n elements
__device__ __forceinline__ uint32_t rbits(uint32_t ka, uint32_t kb,
                                          uint32_t i, uint32_t n) {
#if PARTITIONABLE
    uint32_t o0, o1;
    tf2x32(ka, kb, 0u, i, o0, o1);
    return o0 ^ o1;
#else
    uint32_t half = n >> 1, o0, o1;
    if (i < half) { tf2x32(ka, kb, i, i + half, o0, o1); return o0; }
    else          { tf2x32(ka, kb, i - half, i, o0, o1); return o1; }
#endif
}

__device__ __forceinline__ float u01(uint32_t bits) {
    // JAX uniform: bitcast((bits>>9) | 0x3f800000) - 1.0
    return __uint_as_float((bits >> 9) | 0x3F800000u) - 1.0f;
}

__device__ __forceinline__ float sigmoidf_(float x) {
    return 1.0f / (1.0f + expf(-x));
}

__device__ __forceinline__ float softplusf_(float x) {
    return fmaxf(x, 0.0f) + log1pf(expf(-fabsf(x)));
}

__device__ __forceinline__ float warpSum(float v) {
#pragma unroll
    for (int o = 16; o; o >>= 1) v += __shfl_down_sync(0xffffffffu, v, o);
    return v;
}

// ------------------------------ key derivation -----------------------------
__global__ void k_keys(const int* __restrict__ seed) {
    if (threadIdx.x != 0 || blockIdx.x != 0) return;
    uint32_t ck0 = 0u;                       // hi word of int32 seed (jax: 0)
    uint32_t ck1 = (uint32_t)seed[0];
    uint32_t a, b, o0, o1;
#if PARTITIONABLE
    // split(key): child_i = cipher(key, (0, i)); key = child0, k_u0 = child1
    tf2x32(ck0, ck1, 0u, 0u, o0, o1);
    tf2x32(ck0, ck1, 0u, 1u, a, b);
    g_keys[0] = a; g_keys[1] = b;
    ck0 = o0; ck1 = o1;
    for (int t = 0; t < KSTEPS; t++) {
        uint32_t n0, n1;
        tf2x32(ck0, ck1, 0u, 0u, n0, n1);
        tf2x32(ck0, ck1, 0u, 1u, a, b); g_keys[2 + 6*t + 0] = a; g_keys[2 + 6*t + 1] = b;
        tf2x32(ck0, ck1, 0u, 2u, a, b); g_keys[2 + 6*t + 2] = a; g_keys[2 + 6*t + 3] = b;
        tf2x32(ck0, ck1, 0u, 3u, a, b); g_keys[2 + 6*t + 4] = a; g_keys[2 + 6*t + 5] = b;
        ck0 = n0; ck1 = n1;
    }
#else
    // original split: counts iota(2n), halves, keys[j]=(out[2j],out[2j+1])
    uint32_t a0, a1, b0, b1;
    tf2x32(ck0, ck1, 0u, 2u, a0, b0);
    tf2x32(ck0, ck1, 1u, 3u, a1, b1);
    g_keys[0] = b0; g_keys[1] = b1;     // k_u0
    ck0 = a0; ck1 = a1;                 // new key
    for (int t = 0; t < KSTEPS; t++) {
        uint32_t q0[4], q1[4];
        for (int i = 0; i < 4; i++)
            tf2x32(ck0, ck1, (uint32_t)i, (uint32_t)(i + 4), q0[i], q1[i]);
        g_keys[2 + 6*t + 0] = q0[2]; g_keys[2 + 6*t + 1] = q0[3];  // k1
        g_keys[2 + 6*t + 2] = q1[0]; g_keys[2 + 6*t + 3] = q1[1];  // k2
        g_keys[2 + 6*t + 4] = q1[2]; g_keys[2 + 6*t + 5] = q1[3];  // k3
        ck0 = q0[0]; ck1 = q0[1];
    }
#endif
}

// ------------------------------ setup kernels ------------------------------
__global__ void k_copy(const float* __restrict__ src, float* __restrict__ dst, int n4) {
    int i = blockIdx.x * blockDim.x + threadIdx.x;
    if (i < n4) ((float4*)dst)[i] = ((const float4*)src)[i];
}

__global__ void k_transpose(const float* __restrict__ W, float* __restrict__ Wt) {
    __shared__ float tile[32][33];
    int x = blockIdx.x * 32 + threadIdx.x;
    int y0 = blockIdx.y * 32;
    for (int j = threadIdx.y; j < 32; j += 8)
        tile[j][threadIdx.x] = W[(size_t)(y0 + j) * Hn + x];
    __syncthreads();
    int x2 = blockIdx.y * 32 + threadIdx.x;
    int y2 = blockIdx.x * 32;
    for (int j = threadIdx.y; j < 32; j += 8)
        Wt[(size_t)(y2 + j) * Vn + x2] = tile[threadIdx.x][j];
}

__global__ void k_wcol(const float* __restrict__ W) {
    int h = blockIdx.x * 256 + threadIdx.x;
    if (h < Hn) {
        float s = 0.0f;
        for (int v = 0; v < Vn; v++) s += W[(size_t)v * Hn + h];
        g_wcol[h] = s;
    }
}

__global__ void k_bsum(const float* __restrict__ b) {
    float s = 0.0f;
    for (int j = threadIdx.x; j < Vn; j += 256) s += b[j];
    __shared__ float sh[8];
    float w = warpSum(s);
    if ((threadIdx.x & 31) == 0) sh[threadIdx.x >> 5] = w;
    __syncthreads();
    if (threadIdx.x == 0) {
        float t = 0.0f;
        for (int k = 0; k < 8; k++) t += sh[k];
        g_bsum = t;
        g_acc[0] = 0.0;
        g_acc[1] = 0.0;
    }
}

__global__ void k_u0() {
    int i = blockIdx.x * 256 + threadIdx.x;
    if (i < Bn) {
        uint32_t bits = rbits(g_keys[0], g_keys[1], (uint32_t)i, Bn);
        g_u[i] = (u01(bits) < 0.5f) ? 1.0f : 0.0f;
    }
}

// ------------------------------ Gibbs kernels ------------------------------
__global__ void k_vbranch() {
    int i = blockIdx.x * 256 + threadIdx.x;
    float u = g_u[i >> 10];      // Vn = 1024
    float v = g_v[i];
    g_vbr[i] = (u != 0.0f) ? v : 1.0f - v;
}

__global__ void k_hidden(const float* __restrict__ c, int koff) {
    int i = blockIdx.x * 256 + threadIdx.x;
    uint32_t ka = g_keys[koff], kb = g_keys[koff + 1];
    float p = sigmoidf_(g_s[i] + c[i & (Hn - 1)]);
    uint32_t bits = rbits(ka, kb, (uint32_t)i, (uint32_t)(Bn * Hn));
    g_h[i] = (u01(bits) < p) ? 1.0f : 0.0f;
}

__global__ void k_dE(const float* __restrict__ bb, int koff) {
    int row = blockIdx.x;
    const float* arow = g_a + (size_t)row * Vn;
    const float* vrow = g_v + (size_t)row * Vn;
    float asum = 0.0f, va = 0.0f, vb = 0.0f;
    for (int j = threadIdx.x; j < Vn; j += 256) {
        float av = arow[j], vv = vrow[j];
        asum += av; va += vv * av; vb += vv * bb[j];
    }
    __shared__ float sh[3][8];
    float w0 = warpSum(asum), w1 = warpSum(va), w2 = warpSum(vb);
    int lane = threadIdx.x & 31, wid = threadIdx.x >> 5;
    if (lane == 0) { sh[0][wid] = w0; sh[1][wid] = w1; sh[2][wid] = w2; }
    __syncthreads();
    if (threadIdx.x == 0) {
        float A = 0, Va = 0, Vb = 0;
        for (int k = 0; k < 8; k++) { A += sh[0][k]; Va += sh[1][k]; Vb += sh[2][k]; }
        float dE = -g_bsum - A + 2.0f * Vb + 2.0f * Va;
        float pu = sigmoidf_(dE);
        uint32_t bits = rbits(g_keys[koff], g_keys[koff + 1], (uint32_t)row, Bn);
        g_u[row] = (u01(bits) < pu) ? 1.0f : 0.0f;
    }
}

__global__ void k_vupd(const float* __restrict__ bb, int koff) {
    int i = blockIdx.x * 256 + threadIdx.x;
    uint32_t ka = g_keys[koff], kb = g_keys[koff + 1];
    float p = sigmoidf_(g_a[i] + bb[i & (Vn - 1)]);
    uint32_t bits = rbits(ka, kb, (uint32_t)i, (uint32_t)(Bn * Vn));
    float vn = (u01(bits) < p) ? 1.0f : 0.0f;
    float un = g_u[i >> 10];
    g_v[i] = (un != 0.0f) ? vn : 1.0f - vn;
}

// ------------------------------ free energy --------------------------------
__global__ void k_fe(const float* __restrict__ v, const float* __restrict__ bb,
                     const float* __restrict__ cc, int accIdx) {
    int row = blockIdx.x;
    const float* srow = g_s + (size_t)row * Hn;
    const float* vrow = v + (size_t)row * Vn;
    float sp1 = 0.0f, sp2 = 0.0f, vb = 0.0f;
    for (int j = threadIdx.x; j < Hn; j += 256) {
        float s = srow[j];
        sp1 += softplusf_(s + cc[j]);
        sp2 += softplusf_(g_wcol[j] - s + cc[j]);
    }
    for (int j = threadIdx.x; j < Vn; j += 256) vb += vrow[j] * bb[j];
    __shared__ float sh[3][8];
    float w0 = warpSum(sp1), w1 = warpSum(sp2), w2 = warpSum(vb);
    int lane = threadIdx.x & 31, wid = threadIdx.x >> 5;
    if (lane == 0) { sh[0][wid] = w0; sh[1][wid] = w1; sh[2][wid] = w2; }
    __syncthreads();
    if (threadIdx.x == 0) {
        float S1 = 0, S2 = 0, VB = 0;
        for (int k = 0; k < 8; k++) { S1 += sh[0][k]; S2 += sh[1][k]; VB += sh[2][k]; }
        float nfn = VB - S1;                       // negF_normal
        float nff = (g_bsum - VB) - S2;            // negF_flip
        float m = fmaxf(nfn, nff);
        float F = -(m + log1pf(expf(fminf(nfn, nff) - m)));
        atomicAdd(&g_acc[accIdx], (double)F);
    }
}

__global__ void k_final(float* __restrict__ out) {
    if (threadIdx.x == 0 && blockIdx.x == 0)
        out[0] = (float)((g_acc[0] - g_acc[1]) * (1.0 / (double)Bn));
}

// ------------------------------ SGEMM 8192x1024x1024 -----------------------
// C[8192,1024] = A[8192,1024] @ B[1024,1024], all row-major fp32.
__global__ __launch_bounds__(256) void k_gemm(const float* __restrict__ A,
                                              const float* __restrict__ Bm,
                                              float* __restrict__ C) {
    const int K = 1024, N = 1024;
    __shared__ float As[8][128];
    __shared__ float Bs[8][128];
    const int cRow = blockIdx.y;   // M tile (128 rows)
    const int cCol = blockIdx.x;   // N tile (128 cols)
    const int tid = threadIdx.x;
    const int trow = tid >> 4;     // 0..15
    const int tcol = tid & 15;     // 0..15
    const int aRow = tid >> 1;          // 0..127
    const int aCol = (tid & 1) << 2;    // 0 or 4
    const int bRow = tid >> 5;          // 0..7
    const int bCol = (tid & 31) << 2;   // 0..124

    const float* Ablk = A + (size_t)cRow * 128 * K;
    const float* Bblk = Bm + (size_t)cCol * 128;

    float acc[8][8];
#pragma unroll
    for (int m = 0; m < 8; m++)
#pragma unroll
        for (int n = 0; n < 8; n++) acc[m][n] = 0.0f;

    for (int k0 = 0; k0 < K; k0 += 8) {
        float4 a4 = *(const float4*)(Ablk + (size_t)aRow * K + k0 + aCol);
        As[aCol + 0][aRow] = a4.x;
        As[aCol + 1][aRow] = a4.y;
        As[aCol + 2][aRow] = a4.z;
        As[aCol + 3][aRow] = a4.w;
        float4 b4 = *(const float4*)(Bblk + (size_t)(k0 + bRow) * N + bCol);
        *(float4*)&Bs[bRow][bCol] = b4;
        __syncthreads();
#pragma unroll
        for (int kk = 0; kk < 8; kk++) {
            float regM[8], regN[8];
            float4 m0 = *(const float4*)&As[kk][trow * 8];
            float4 m1 = *(const float4*)&As[kk][trow * 8 + 4];
            regM[0] = m0.x; regM[1] = m0.y; regM[2] = m0.z; regM[3] = m0.w;
            regM[4] = m1.x; regM[5] = m1.y; regM[6] = m1.z; regM[7] = m1.w;
            float4 n0 = *(const float4*)&Bs[kk][tcol * 8];
            float4 n1 = *(const float4*)&Bs[kk][tcol * 8 + 4];
            regN[0] = n0.x; regN[1] = n0.y; regN[2] = n0.z; regN[3] = n0.w;
            regN[4] = n1.x; regN[5] = n1.y; regN[6] = n1.z; regN[7] = n1.w;
#pragma unroll
            for (int m = 0; m < 8; m++)
#pragma unroll
                for (int n = 0; n < 8; n++)
                    acc[m][n] += regM[m] * regN[n];
        }
        __syncthreads();
    }

    float* Cblk = C + (size_t)(cRow * 128 + trow * 8) * N + cCol * 128 + tcol * 8;
#pragma unroll
    for (int m = 0; m < 8; m++) {
        float4 r0 = make_float4(acc[m][0], acc[m][1], acc[m][2], acc[m][3]);
        float4 r1 = make_float4(acc[m][4], acc[m][5], acc[m][6], acc[m][7]);
        *(float4*)(Cblk + (size_t)m * N)     = r0;
        *(float4*)(Cblk + (size_t)m * N + 4) = r1;
    }
}

// ------------------------------ launch -------------------------------------
extern "C" void kernel_launch(void* const* d_in, const int* in_sizes, int n_in,
                              void* d_out, int out_size) {
    const float* v_data = (const float*)d_in[0];
    const float* W      = (const float*)d_in[1];
    const float* b      = (const float*)d_in[2];
    const float* c      = (const float*)d_in[3];
    const int*   seed   = (const int*)d_in[4];
    float* out = (float*)d_out;

    float *p_v, *p_vbr, *p_s, *p_h, *p_a, *p_Wt;
    cudaGetSymbolAddress((void**)&p_v,   g_v);
    cudaGetSymbolAddress((void**)&p_vbr, g_vbr);
    cudaGetSymbolAddress((void**)&p_s,   g_s);
    cudaGetSymbolAddress((void**)&p_h,   g_h);
    cudaGetSymbolAddress((void**)&p_a,   g_a);
    cudaGetSymbolAddress((void**)&p_Wt,  g_Wt);

    dim3 ggrid(Vn / 128, Bn / 128);   // (8, 64)

    k_keys<<<1, 32>>>(seed);
    k_copy<<<(Bn * Vn / 4 + 255) / 256, 256>>>(v_data, p_v, Bn * Vn / 4);
    k_transpose<<<dim3(Hn / 32, Vn / 32), dim3(32, 8)>>>(W, p_Wt);
    k_wcol<<<Hn / 256, 256>>>(W);
    k_bsum<<<1, 256>>>(b);
    k_u0<<<Bn / 256, 256>>>();

    for (int t = 0; t < KSTEPS; t++) {
        int koff = 2 + 6 * t;
        k_vbranch<<<Bn * Vn / 256, 256>>>();
        k_gemm<<<ggrid, 256>>>(p_vbr, W, p_s);           // s = v_branch @ W
        k_hidden<<<Bn * Hn / 256, 256>>>(c, koff);       // h ~ bern(sigmoid(s+c))
        k_gemm<<<ggrid, 256>>>(p_h, p_Wt, p_a);          // a = h @ W^T
        k_dE<<<Bn, 256>>>(b, koff + 2);                  // u_new ~ bern(sigmoid(dE))
        k_vupd<<<Bn * Vn / 256, 256>>>(b, koff + 4);     // v ~ sym-flip(bern(sigmoid(a+b)))
    }

    k_gemm<<<ggrid, 256>>>(v_data, W, p_s);
    k_fe<<<Bn, 256>>>(v_data, b, c, 0);
    k_gemm<<<ggrid, 256>>>(p_v, W, p_s);
    k_fe<<<Bn, 256>>>(p_v, b, c, 1);
    k_final<<<1, 1>>>(out);
}

// round 2
// speedup vs baseline: 1.0547x; 1.0547x over previous
#include <cuda_runtime.h>
#include <stdint.h>

// ---------------------------------------------------------------------------
// SymmetricRBM: CD-k loss with symmetrized free energy, bit-exact JAX threefry.
// ---------------------------------------------------------------------------

#define PARTITIONABLE 1   // jax_threefry_partitionable (default True since jax 0.4.36)

#define Bn 8192
#define Vn 1024
#define Hn 1024
#define KSTEPS 10

// ------------------------- scratch (device globals) -------------------------
__device__ float    g_v[Bn * Vn];     // chain state v
__device__ float    g_vbr[Bn * Vn];   // v_branch
__device__ float    g_s[Bn * Hn];     // pre-activations / vW scratch
__device__ float    g_h[Bn * Hn];     // hidden samples
__device__ float    g_a[Bn * Vn];     // h @ W^T
__device__ float    g_Wt[Hn * Vn];    // W transpose
__device__ float    g_wcol[Hn];       // W.sum(axis=0)
__device__ float    g_u[Bn];          // flip indicator u
__device__ float    g_bsum;           // b.sum()
__device__ uint32_t g_keys[2 + 6 * KSTEPS];
__device__ double   g_acc[2];         // sum F(v_data), sum F(v_model)

// ------------------------------ threefry2x32 -------------------------------
__device__ __forceinline__ uint32_t rotl_(uint32_t x, int r) {
    return (x << r) | (x >> (32 - r));
}

__device__ __forceinline__ void tf2x32(uint32_t k0, uint32_t k1,
                                       uint32_t x0, uint32_t x1,
                                       uint32_t& o0, uint32_t& o1) {
    uint32_t ks2 = k0 ^ k1 ^ 0x1BD11BDAu;
    x0 += k0; x1 += k1;
#define TF_R4(a,b,c,d) \
    x0 += x1; x1 = rotl_(x1, a); x1 ^= x0; \
    x0 += x1; x1 = rotl_(x1, b); x1 ^= x0; \
    x0 += x1; x1 = rotl_(x1, c); x1 ^= x0; \
    x0 += x1; x1 = rotl_(x1, d); x1 ^= x0;
    TF_R4(13, 15, 26, 6)
    x0 += k1;  x1 += ks2 + 1u;
    TF_R4(17, 29, 16, 24)
    x0 += ks2; x1 += k0 + 2u;
    TF_R4(13, 15, 26, 6)
    x0 += k0;  x1 += k1 + 3u;
    TF_R4(17, 29, 16, 24)
    x0 += k1;  x1 += ks2 + 4u;
    TF_R4(13, 15, 26, 6)
    x0 += ks2; x1 += k0 + 5u;
#undef TF_R4
    o0 = x0; o1 = x1;
}

// random bits for flat index i in an array of n elements
__device__ __forceinline__ uint32_t rbits(uint32_t ka, uint32_t kb,
                                          uint32_t i, uint32_t n) {
#if PARTITIONABLE
    uint32_t o0, o1;
    tf2x32(ka, kb, 0u, i, o0, o1);
    return o0 ^ o1;
#else
    uint32_t half = n >> 1, o0, o1;
    if (i < half) { tf2x32(ka, kb, i, i + half, o0, o1); return o0; }
    else          { tf2x32(ka, kb, i - half, i, o0, o1); return o1; }
#endif
}

__device__ __forceinline__ float u01(uint32_t bits) {
    // JAX uniform: bitcast((bits>>9) | 0x3f800000) - 1.0
    return __uint_as_float((bits >> 9) | 0x3F800000u) - 1.0f;
}

__device__ __forceinline__ float sigmoidf_(float x) {
    return 1.0f / (1.0f + expf(-x));
}

__device__ __forceinline__ float softplusf_(float x) {
    return fmaxf(x, 0.0f) + log1pf(expf(-fabsf(x)));
}

__device__ __forceinline__ float warpSum(float v) {
#pragma unroll
    for (int o = 16; o; o >>= 1) v += __shfl_down_sync(0xffffffffu, v, o);
    return v;
}

// ------------------------------ key derivation -----------------------------
__global__ void k_keys(const int* __restrict__ seed) {
    if (threadIdx.x != 0 || blockIdx.x != 0) return;
    uint32_t ck0 = 0u;                       // hi word of int32 seed (jax: 0)
    uint32_t ck1 = (uint32_t)seed[0];
    uint32_t a, b, o0, o1;
#if PARTITIONABLE
    // split(key): child_i = cipher(key, (0, i)); key = child0, k_u0 = child1
    tf2x32(ck0, ck1, 0u, 0u, o0, o1);
    tf2x32(ck0, ck1, 0u, 1u, a, b);
    g_keys[0] = a; g_keys[1] = b;
    ck0 = o0; ck1 = o1;
    for (int t = 0; t < KSTEPS; t++) {
        uint32_t n0, n1;
        tf2x32(ck0, ck1, 0u, 0u, n0, n1);
        tf2x32(ck0, ck1, 0u, 1u, a, b); g_keys[2 + 6*t + 0] = a; g_keys[2 + 6*t + 1] = b;
        tf2x32(ck0, ck1, 0u, 2u, a, b); g_keys[2 + 6*t + 2] = a; g_keys[2 + 6*t + 3] = b;
        tf2x32(ck0, ck1, 0u, 3u, a, b); g_keys[2 + 6*t + 4] = a; g_keys[2 + 6*t + 5] = b;
        ck0 = n0; ck1 = n1;
    }
#else
    // original split: counts iota(2n), halves, keys[j]=(out[2j],out[2j+1])
    uint32_t a0, a1, b0, b1;
    tf2x32(ck0, ck1, 0u, 2u, a0, b0);
    tf2x32(ck0, ck1, 1u, 3u, a1, b1);
    g_keys[0] = b0; g_keys[1] = b1;     // k_u0
    ck0 = a0; ck1 = a1;                 // new key
    for (int t = 0; t < KSTEPS; t++) {
        uint32_t q0[4], q1[4];
        for (int i = 0; i < 4; i++)
            tf2x32(ck0, ck1, (uint32_t)i, (uint32_t)(i + 4), q0[i], q1[i]);
        g_keys[2 + 6*t + 0] = q0[2]; g_keys[2 + 6*t + 1] = q0[3];  // k1
        g_keys[2 + 6*t + 2] = q1[0]; g_keys[2 + 6*t + 3] = q1[1];  // k2
        g_keys[2 + 6*t + 4] = q1[2]; g_keys[2 + 6*t + 5] = q1[3];  // k3
        ck0 = q0[0]; ck1 = q0[1];
    }
#endif
}

// ------------------------------ setup kernels ------------------------------
__global__ void k_copy(const float* __restrict__ src, float* __restrict__ dst, int n4) {
    int i = blockIdx.x * blockDim.x + threadIdx.x;
    if (i < n4) ((float4*)dst)[i] = ((const float4*)src)[i];
}

__global__ void k_transpose(const float* __restrict__ W, float* __restrict__ Wt) {
    __shared__ float tile[32][33];
    int x = blockIdx.x * 32 + threadIdx.x;
    int y0 = blockIdx.y * 32;
    for (int j = threadIdx.y; j < 32; j += 8)
        tile[j][threadIdx.x] = W[(size_t)(y0 + j) * Hn + x];
    __syncthreads();
    int x2 = blockIdx.y * 32 + threadIdx.x;
    int y2 = blockIdx.x * 32;
    for (int j = threadIdx.y; j < 32; j += 8)
        Wt[(size_t)(y2 + j) * Vn + x2] = tile[threadIdx.x][j];
}

__global__ void k_wcol(const float* __restrict__ W) {
    int h = blockIdx.x * 256 + threadIdx.x;
    if (h < Hn) {
        float s = 0.0f;
        for (int v = 0; v < Vn; v++) s += W[(size_t)v * Hn + h];
        g_wcol[h] = s;
    }
}

__global__ void k_bsum(const float* __restrict__ b) {
    float s = 0.0f;
    for (int j = threadIdx.x; j < Vn; j += 256) s += b[j];
    __shared__ float sh[8];
    float w = warpSum(s);
    if ((threadIdx.x & 31) == 0) sh[threadIdx.x >> 5] = w;
    __syncthreads();
    if (threadIdx.x == 0) {
        float t = 0.0f;
        for (int k = 0; k < 8; k++) t += sh[k];
        g_bsum = t;
        g_acc[0] = 0.0;
        g_acc[1] = 0.0;
    }
}

__global__ void k_u0() {
    int i = blockIdx.x * 256 + threadIdx.x;
    if (i < Bn) {
        uint32_t bits = rbits(g_keys[0], g_keys[1], (uint32_t)i, Bn);
        g_u[i] = (u01(bits) < 0.5f) ? 1.0f : 0.0f;
    }
}

// ------------------------------ Gibbs kernels ------------------------------
__global__ void k_vbranch() {
    int i = blockIdx.x * 256 + threadIdx.x;
    float u = g_u[i >> 10];      // Vn = 1024
    float v = g_v[i];
    g_vbr[i] = (u != 0.0f) ? v : 1.0f - v;
}

__global__ void k_hidden(const float* __restrict__ c, int koff) {
    int i = blockIdx.x * 256 + threadIdx.x;
    uint32_t ka = g_keys[koff], kb = g_keys[koff + 1];
    float p = sigmoidf_(g_s[i] + c[i & (Hn - 1)]);
    uint32_t bits = rbits(ka, kb, (uint32_t)i, (uint32_t)(Bn * Hn));
    g_h[i] = (u01(bits) < p) ? 1.0f : 0.0f;
}

__global__ void k_dE(const float* __restrict__ bb, int koff) {
    int row = blockIdx.x;
    const float* arow = g_a + (size_t)row * Vn;
    const float* vrow = g_v + (size_t)row * Vn;
    float asum = 0.0f, va = 0.0f, vb = 0.0f;
    for (int j = threadIdx.x; j < Vn; j += 256) {
        float av = arow[j], vv = vrow[j];
        asum += av; va += vv * av; vb += vv * bb[j];
    }
    __shared__ float sh[3][8];
    float w0 = warpSum(asum), w1 = warpSum(va), w2 = warpSum(vb);
    int lane = threadIdx.x & 31, wid = threadIdx.x >> 5;
    if (lane == 0) { sh[0][wid] = w0; sh[1][wid] = w1; sh[2][wid] = w2; }
    __syncthreads();
    if (threadIdx.x == 0) {
        float A = 0, Va = 0, Vb = 0;
        for (int k = 0; k < 8; k++) { A += sh[0][k]; Va += sh[1][k]; Vb += sh[2][k]; }
        float dE = -g_bsum - A + 2.0f * Vb + 2.0f * Va;
        float pu = sigmoidf_(dE);
        uint32_t bits = rbits(g_keys[koff], g_keys[koff + 1], (uint32_t)row, Bn);
        g_u[row] = (u01(bits) < pu) ? 1.0f : 0.0f;
    }
}

__global__ void k_vupd(const float* __restrict__ bb, int koff) {
    int i = blockIdx.x * 256 + threadIdx.x;
    uint32_t ka = g_keys[koff], kb = g_keys[koff + 1];
    float p = sigmoidf_(g_a[i] + bb[i & (Vn - 1)]);
    uint32_t bits = rbits(ka, kb, (uint32_t)i, (uint32_t)(Bn * Vn));
    float vn = (u01(bits) < p) ? 1.0f : 0.0f;
    float un = g_u[i >> 10];
    g_v[i] = (un != 0.0f) ? vn : 1.0f - vn;
}

// ------------------------------ free energy --------------------------------
__global__ void k_fe(const float* __restrict__ v, const float* __restrict__ bb,
                     const float* __restrict__ cc, int accIdx) {
    int row = blockIdx.x;
    const float* srow = g_s + (size_t)row * Hn;
    const float* vrow = v + (size_t)row * Vn;
    float sp1 = 0.0f, sp2 = 0.0f, vb = 0.0f;
    for (int j = threadIdx.x; j < Hn; j += 256) {
        float s = srow[j];
        sp1 += softplusf_(s + cc[j]);
        sp2 += softplusf_(g_wcol[j] - s + cc[j]);
    }
    for (int j = threadIdx.x; j < Vn; j += 256) vb += vrow[j] * bb[j];
    __shared__ float sh[3][8];
    float w0 = warpSum(sp1), w1 = warpSum(sp2), w2 = warpSum(vb);
    int lane = threadIdx.x & 31, wid = threadIdx.x >> 5;
    if (lane == 0) { sh[0][wid] = w0; sh[1][wid] = w1; sh[2][wid] = w2; }
    __syncthreads();
    if (threadIdx.x == 0) {
        float S1 = 0, S2 = 0, VB = 0;
        for (int k = 0; k < 8; k++) { S1 += sh[0][k]; S2 += sh[1][k]; VB += sh[2][k]; }
        float nfn = VB - S1;                       // negF_normal
        float nff = (g_bsum - VB) - S2;            // negF_flip
        float m = fmaxf(nfn, nff);
        float F = -(m + log1pf(expf(fminf(nfn, nff) - m)));
        atomicAdd(&g_acc[accIdx], (double)F);
    }
}

__global__ void k_final(float* __restrict__ out) {
    if (threadIdx.x == 0 && blockIdx.x == 0)
        out[0] = (float)((g_acc[0] - g_acc[1]) * (1.0 / (double)Bn));
}

// ------------------------------ SGEMM 8192x1024x1024 -----------------------
// C[8192,1024] = A[8192,1024] @ B[1024,1024], all row-major fp32.
__global__ __launch_bounds__(256) void k_gemm(const float* __restrict__ A,
                                              const float* __restrict__ Bm,
                                              float* __restrict__ C) {
    const int K = 1024, N = 1024;
    __shared__ float As[8][128];
    __shared__ float Bs[8][128];
    const int cRow = blockIdx.y;   // M tile (128 rows)
    const int cCol = blockIdx.x;   // N tile (128 cols)
    const int tid = threadIdx.x;
    const int trow = tid >> 4;     // 0..15
    const int tcol = tid & 15;     // 0..15
    const int aRow = tid >> 1;          // 0..127
    const int aCol = (tid & 1) << 2;    // 0 or 4
    const int bRow = tid >> 5;          // 0..7
    const int bCol = (tid & 31) << 2;   // 0..124

    const float* Ablk = A + (size_t)cRow * 128 * K;
    const float* Bblk = Bm + (size_t)cCol * 128;

    float acc[8][8];
#pragma unroll
    for (int m = 0; m < 8; m++)
#pragma unroll
        for (int n = 0; n < 8; n++) acc[m][n] = 0.0f;

    for (int k0 = 0; k0 < K; k0 += 8) {
        float4 a4 = *(const float4*)(Ablk + (size_t)aRow * K + k0 + aCol);
        As[aCol + 0][aRow] = a4.x;
        As[aCol + 1][aRow] = a4.y;
        As[aCol + 2][aRow] = a4.z;
        As[aCol + 3][aRow] = a4.w;
        float4 b4 = *(const float4*)(Bblk + (size_t)(k0 + bRow) * N + bCol);
        *(float4*)&Bs[bRow][bCol] = b4;
        __syncthreads();
#pragma unroll
        for (int kk = 0; kk < 8; kk++) {
            float regM[8], regN[8];
            float4 m0 = *(const float4*)&As[kk][trow * 8];
            float4 m1 = *(const float4*)&As[kk][trow * 8 + 4];
            regM[0] = m0.x; regM[1] = m0.y; regM[2] = m0.z; regM[3] = m0.w;
            regM[4] = m1.x; regM[5] = m1.y; regM[6] = m1.z; regM[7] = m1.w;
            float4 n0 = *(const float4*)&Bs[kk][tcol * 8];
            float4 n1 = *(const float4*)&Bs[kk][tcol * 8 + 4];
            regN[0] = n0.x; regN[1] = n0.y; regN[2] = n0.z; regN[3] = n0.w;
            regN[4] = n1.x; regN[5] = n1.y; regN[6] = n1.z; regN[7] = n1.w;
#pragma unroll
            for (int m = 0; m < 8; m++)
#pragma unroll
                for (int n = 0; n < 8; n++)
                    acc[m][n] += regM[m] * regN[n];
        }
        __syncthreads();
    }

    float* Cblk = C + (size_t)(cRow * 128 + trow * 8) * N + cCol * 128 + tcol * 8;
#pragma unroll
    for (int m = 0; m < 8; m++) {
        float4 r0 = make_float4(acc[m][0], acc[m][1], acc[m][2], acc[m][3]);
        float4 r1 = make_float4(acc[m][4], acc[m][5], acc[m][6], acc[m][7]);
        *(float4*)(Cblk + (size_t)m * N)     = r0;
        *(float4*)(Cblk + (size_t)m * N + 4) = r1;
    }
}

// ------------------------------ launch -------------------------------------
extern "C" void kernel_launch(void* const* d_in, const int* in_sizes, int n_in,
                              void* d_out, int out_size) {
    const float* v_data = (const float*)d_in[0];
    const float* W      = (const float*)d_in[1];
    const float* b      = (const float*)d_in[2];
    const float* c      = (const float*)d_in[3];
    const int*   seed   = (const int*)d_in[4];
    float* out = (float*)d_out;

    float *p_v, *p_vbr, *p_s, *p_h, *p_a, *p_Wt;
    cudaGetSymbolAddress((void**)&p_v,   g_v);
    cudaGetSymbolAddress((void**)&p_vbr, g_vbr);
    cudaGetSymbolAddress((void**)&p_s,   g_s);
    cudaGetSymbolAddress((void**)&p_h,   g_h);
    cudaGetSymbolAddress((void**)&p_a,   g_a);
    cudaGetSymbolAddress((void**)&p_Wt,  g_Wt);

    dim3 ggrid(Vn / 128, Bn / 128);   // (8, 64)

    k_keys<<<1, 32>>>(seed);
    k_copy<<<(Bn * Vn / 4 + 255) / 256, 256>>>(v_data, p_v, Bn * Vn / 4);
    k_transpose<<<dim3(Hn / 32, Vn / 32), dim3(32, 8)>>>(W, p_Wt);
    k_wcol<<<Hn / 256, 256>>>(W);
    k_bsum<<<1, 256>>>(b);
    k_u0<<<Bn / 256, 256>>>();

    for (int t = 0; t < KSTEPS; t++) {
        int koff = 2 + 6 * t;
        k_vbranch<<<Bn * Vn / 256, 256>>>();
        k_gemm<<<ggrid, 256>>>(p_vbr, W, p_s);           // s = v_branch @ W
        k_hidden<<<Bn * Hn / 256, 256>>>(c, koff);       // h ~ bern(sigmoid(s+c))
        k_gemm<<<ggrid, 256>>>(p_h, p_Wt, p_a);          // a = h @ W^T
        k_dE<<<Bn, 256>>>(b, koff + 2);                  // u_new ~ bern(sigmoid(dE))
        k_vupd<<<Bn * Vn / 256, 256>>>(b, koff + 4);     // v ~ sym-flip(bern(sigmoid(a+b)))
    }

    k_gemm<<<ggrid, 256>>>(v_data, W, p_s);
    k_fe<<<Bn, 256>>>(v_data, b, c, 0);
    k_gemm<<<ggrid, 256>>>(p_v, W, p_s);
    k_fe<<<Bn, 256>>>(p_v, b, c, 1);
    k_final<<<1, 1>>>(out);
}